// round 6
// baseline (speedup 1.0000x reference)
#include <cuda_runtime.h>
#include <math.h>

#define CH 128
#define CH4 (CH / 4)
#define TPB 512          // 16 warps
#define BLOCKS (152 * 3) // GB300: 152 SMs, 3 blocks/SM resident

// Reparameterization constants (match reference, fp64 -> fp32 rounding)
#define PED_F         1.4551915228366852e-11f   // 2^-36, exact in fp32
#define GAMMA_BOUND_F 3.814697265625e-06f       // 2^-18, exact in fp32
#define BETA_BOUND_F  1.0000072759311444e-03f   // sqrt(1e-6 + 2^-36)

__device__ __forceinline__ float reparam_g(float g) {
    float t = fmaxf(g, GAMMA_BOUND_F);
    return t * t - PED_F;
}

// ---------------------------------------------------------------------------
// Single fused kernel, cheap prologue:
//   - 16 warps x 8 gamma rows each, one coalesced LDG.128 per row per warp
//   - thread-private "off-diagonal nonzero" bit; diagonal lane writes sdv[row]
//   - one __syncthreads_or gives the block-level "g is diagonal" verdict
// Fast path: pure elementwise float4 stream (streaming hints, 4-deep
// pipeline). Fallback: dense per-row recompute (correct for any gamma).
// ---------------------------------------------------------------------------
__global__ void __launch_bounds__(TPB)
gdn_fused(const float* __restrict__ x,
          const float* __restrict__ beta,
          const float* __restrict__ gamma,
          float* __restrict__ out, unsigned n4) {
    __shared__ __align__(16) float sb[CH];
    __shared__ __align__(16) float sdv[CH];

    const int tid  = threadIdx.x;
    const int w    = tid >> 5;
    const int lane = tid & 31;

    if (tid < CH) {
        float bb = fmaxf(__ldg(&beta[tid]), BETA_BOUND_F);
        sb[tid] = bb * bb - PED_F;
    }

    // prologue: warp w checks rows 8w .. 8w+7
    int nz = 0;
#pragma unroll
    for (int r = 0; r < 8; ++r) {
        int row = w * 8 + r;
        float4 g4 = __ldg(&((const float4*)(gamma + (size_t)row * CH))[lane]);
        float gv[4] = {reparam_g(g4.x), reparam_g(g4.y),
                       reparam_g(g4.z), reparam_g(g4.w)};
        if (lane == (row >> 2)) {
            // this lane's 4-element segment contains the diagonal
            sdv[row] = gv[row & 3];
            gv[row & 3] = 0.0f;          // exclude diagonal from the check
        }
        nz |= (gv[0] != 0.0f) | (gv[1] != 0.0f) |
              (gv[2] != 0.0f) | (gv[3] != 0.0f);
    }
    const int bad = __syncthreads_or(nz);   // barrier + block-wide OR

    const unsigned stride = gridDim.x * blockDim.x;   // multiple of 32
    unsigned i = blockIdx.x * blockDim.x + tid;

    const int c4 = (int)(i & (CH4 - 1));   // fixed channel-group
    const int c0 = c4 * 4;

    const float4* __restrict__ x4   = (const float4*)x;
    float4* __restrict__       out4 = (float4*)out;

    const float4 b4 = ((const float4*)sb)[c4];

    if (!bad) {
        const float4 v4 = ((const float4*)sdv)[c4];

#define GDN_ELT(o, xa)                                              \
        o.x = xa.x * rsqrtf(fmaf(v4.x, xa.x * xa.x, b4.x));         \
        o.y = xa.y * rsqrtf(fmaf(v4.y, xa.y * xa.y, b4.y));         \
        o.z = xa.z * rsqrtf(fmaf(v4.z, xa.z * xa.z, b4.z));         \
        o.w = xa.w * rsqrtf(fmaf(v4.w, xa.w * xa.w, b4.w));

        for (; i + 3 * stride < n4; i += 4 * stride) {
            float4 xa = __ldcs(&x4[i]);
            float4 xb = __ldcs(&x4[i + stride]);
            float4 xc = __ldcs(&x4[i + 2 * stride]);
            float4 xd = __ldcs(&x4[i + 3 * stride]);
            float4 oa, ob, oc, od;
            GDN_ELT(oa, xa)
            GDN_ELT(ob, xb)
            GDN_ELT(oc, xc)
            GDN_ELT(od, xd)
            __stcs(&out4[i],              oa);
            __stcs(&out4[i + stride],     ob);
            __stcs(&out4[i + 2 * stride], oc);
            __stcs(&out4[i + 3 * stride], od);
        }
        for (; i < n4; i += stride) {
            float4 xa = __ldcs(&x4[i]);
            float4 oa;
            GDN_ELT(oa, xa)
            __stcs(&out4[i], oa);
        }
#undef GDN_ELT
    } else {
        // Dense fallback: recompute reparam(gamma) row-by-row (any g correct).
        for (; i < n4; i += stride) {
            unsigned row = i >> 5;                 // / CH4
            const float* xr = x + (size_t)row * CH;
            float r[4];
#pragma unroll
            for (int k = 0; k < 4; ++k) {
                int   c   = c0 + k;
                float acc = (k == 0 ? b4.x : k == 1 ? b4.y : k == 2 ? b4.z : b4.w);
                const float* gr = gamma + (size_t)c * CH;
                for (int j = 0; j < CH; ++j) {
                    float gv = reparam_g(gr[j]);
                    float t  = xr[j];
                    acc = fmaf(gv, t * t, acc);
                }
                r[k] = xr[c] * rsqrtf(acc);
            }
            float4 o;
            o.x = r[0]; o.y = r[1]; o.z = r[2]; o.w = r[3];
            out4[i] = o;
        }
    }
}

// ---------------------------------------------------------------------------
extern "C" void kernel_launch(void* const* d_in, const int* in_sizes, int n_in,
                              void* d_out, int out_size) {
    const float* x     = (const float*)d_in[0];
    const float* beta  = (const float*)d_in[1];
    const float* gamma = (const float*)d_in[2];
    float*       out   = (float*)d_out;

    unsigned n4 = (unsigned)(in_sizes[0] / 4);

    gdn_fused<<<BLOCKS, TPB>>>(x, beta, gamma, out, n4);
}

// round 7
// speedup vs baseline: 1.0476x; 1.0476x over previous
#include <cuda_runtime.h>
#include <math.h>

#define CH 128
#define CH4 (CH / 4)
#define TPB 512          // 16 warps
#define BLOCKS (152 * 3) // GB300: 152 SMs, exactly-resident grid

// Reparameterization constants (match reference, fp64 -> fp32 rounding)
#define PED_F         1.4551915228366852e-11f   // 2^-36, exact in fp32
#define GAMMA_BOUND_F 3.814697265625e-06f       // 2^-18, exact in fp32
#define BETA_BOUND_F  1.0000072759311444e-03f   // sqrt(1e-6 + 2^-36)

__device__ __forceinline__ float reparam_g(float g) {
    float t = fmaxf(g, GAMMA_BOUND_F);
    return t * t - PED_F;
}

// ---------------------------------------------------------------------------
// Single fused kernel with prologue/stream overlap:
//   1. issue the first 4-deep batch of streaming x loads (fills HBM pipe)
//   2. gamma prologue: 16 warps x 8 rows, thread-private off-diag-nonzero bit,
//      diagonal lane scatters sdv[row]; verdict via one __syncthreads_or
//   3. fast path consumes the prefetched batch immediately, then streams
// Fallback: dense per-row recompute of reparam(gamma) (correct for any g).
// ---------------------------------------------------------------------------
__global__ void __launch_bounds__(TPB)
gdn_fused(const float* __restrict__ x,
          const float* __restrict__ beta,
          const float* __restrict__ gamma,
          float* __restrict__ out, unsigned n4) {
    __shared__ __align__(16) float sb[CH];
    __shared__ __align__(16) float sdv[CH];

    const int tid  = threadIdx.x;
    const int w    = tid >> 5;
    const int lane = tid & 31;

    const unsigned stride = gridDim.x * blockDim.x;   // multiple of 32
    const unsigned i0 = blockIdx.x * blockDim.x + tid;

    const float4* __restrict__ x4   = (const float4*)x;
    float4* __restrict__       out4 = (float4*)out;

    // ---- 1. prefetch first stream batch (overlaps the prologue) ----
    float4 pa, pb, pc, pd;
    const bool have4 = (i0 + 3 * stride < n4);
    if (have4) {
        pa = __ldcs(&x4[i0]);
        pb = __ldcs(&x4[i0 + stride]);
        pc = __ldcs(&x4[i0 + 2 * stride]);
        pd = __ldcs(&x4[i0 + 3 * stride]);
    }

    // ---- 2. prologue ----
    if (tid < CH) {
        float bb = fmaxf(__ldg(&beta[tid]), BETA_BOUND_F);
        sb[tid] = bb * bb - PED_F;
    }

    int nz = 0;
#pragma unroll
    for (int r = 0; r < 8; ++r) {
        int row = w * 8 + r;
        float4 g4 = __ldg(&((const float4*)(gamma + (size_t)row * CH))[lane]);
        float gv[4] = {reparam_g(g4.x), reparam_g(g4.y),
                       reparam_g(g4.z), reparam_g(g4.w)};
        if (lane == (row >> 2)) {
            sdv[row] = gv[row & 3];
            gv[row & 3] = 0.0f;          // exclude diagonal from the check
        }
        nz |= (gv[0] != 0.0f) | (gv[1] != 0.0f) |
              (gv[2] != 0.0f) | (gv[3] != 0.0f);
    }
    const int bad = __syncthreads_or(nz);   // barrier + block-wide OR

    const int c4 = (int)(i0 & (CH4 - 1));   // fixed channel-group
    const int c0 = c4 * 4;
    const float4 b4 = ((const float4*)sb)[c4];

    unsigned i = i0;

    if (!bad) {
        const float4 v4 = ((const float4*)sdv)[c4];

#define GDN_ELT(o, xa)                                              \
        o.x = xa.x * rsqrtf(fmaf(v4.x, xa.x * xa.x, b4.x));         \
        o.y = xa.y * rsqrtf(fmaf(v4.y, xa.y * xa.y, b4.y));         \
        o.z = xa.z * rsqrtf(fmaf(v4.z, xa.z * xa.z, b4.z));         \
        o.w = xa.w * rsqrtf(fmaf(v4.w, xa.w * xa.w, b4.w));

        // ---- 3a. consume the prefetched batch ----
        if (have4) {
            float4 oa, ob, oc, od;
            GDN_ELT(oa, pa)
            GDN_ELT(ob, pb)
            GDN_ELT(oc, pc)
            GDN_ELT(od, pd)
            __stcs(&out4[i],              oa);
            __stcs(&out4[i + stride],     ob);
            __stcs(&out4[i + 2 * stride], oc);
            __stcs(&out4[i + 3 * stride], od);
            i += 4 * stride;
        }

        // ---- 3b. steady-state stream ----
        for (; i + 3 * stride < n4; i += 4 * stride) {
            float4 xa = __ldcs(&x4[i]);
            float4 xb = __ldcs(&x4[i + stride]);
            float4 xc = __ldcs(&x4[i + 2 * stride]);
            float4 xd = __ldcs(&x4[i + 3 * stride]);
            float4 oa, ob, oc, od;
            GDN_ELT(oa, xa)
            GDN_ELT(ob, xb)
            GDN_ELT(oc, xc)
            GDN_ELT(od, xd)
            __stcs(&out4[i],              oa);
            __stcs(&out4[i + stride],     ob);
            __stcs(&out4[i + 2 * stride], oc);
            __stcs(&out4[i + 3 * stride], od);
        }
        for (; i < n4; i += stride) {
            float4 xa = __ldcs(&x4[i]);
            float4 oa;
            GDN_ELT(oa, xa)
            __stcs(&out4[i], oa);
        }
#undef GDN_ELT
    } else {
        // Dense fallback: recompute reparam(gamma) row-by-row (any g correct).
        for (; i < n4; i += stride) {
            unsigned row = i >> 5;                 // / CH4
            const float* xr = x + (size_t)row * CH;
            float r[4];
#pragma unroll
            for (int k = 0; k < 4; ++k) {
                int   c   = c0 + k;
                float acc = (k == 0 ? b4.x : k == 1 ? b4.y : k == 2 ? b4.z : b4.w);
                const float* gr = gamma + (size_t)c * CH;
                for (int j = 0; j < CH; ++j) {
                    float gv = reparam_g(gr[j]);
                    float t  = xr[j];
                    acc = fmaf(gv, t * t, acc);
                }
                r[k] = xr[c] * rsqrtf(acc);
            }
            float4 o;
            o.x = r[0]; o.y = r[1]; o.z = r[2]; o.w = r[3];
            out4[i] = o;
        }
    }
}

// ---------------------------------------------------------------------------
extern "C" void kernel_launch(void* const* d_in, const int* in_sizes, int n_in,
                              void* d_out, int out_size) {
    const float* x     = (const float*)d_in[0];
    const float* beta  = (const float*)d_in[1];
    const float* gamma = (const float*)d_in[2];
    float*       out   = (float*)d_out;

    unsigned n4 = (unsigned)(in_sizes[0] / 4);

    gdn_fused<<<BLOCKS, TPB>>>(x, beta, gamma, out, n4);
}